// round 1
// baseline (speedup 1.0000x reference)
#include <cuda_runtime.h>

// Problem constants
#define TT 512
#define BB 64
#define HH 768
#define LHD 384
#define G4 1536
#define NLAB 12
#define NEGV (-1000.0f)
#define NBLK_LSTM 96

// ---------------- scratch (static device memory; no allocation) -------------
// X[dir][t][col][b], col = gate*384 + j   (2*512*1536*64)
__device__ float g_X[100663296];
// Hseq[dir][t][j][b]                      (2*512*384*64)
__device__ float g_Hseq[25165824];
// C[dir][b][j]
__device__ float g_C[2 * 64 * 384];
// feats[b][t][l]
__device__ float g_feats[64 * 512 * 12];

__device__ unsigned g_bar = 0u;
__device__ volatile unsigned g_gen = 0u;

__device__ __forceinline__ float sigm(float x) {
    return 1.0f / (1.0f + __expf(-x));
}

__device__ __forceinline__ void gridbar() {
    __syncthreads();
    if (threadIdx.x == 0) {
        __threadfence();
        unsigned gen = g_gen;
        if (atomicAdd(&g_bar, 1u) == (unsigned)(NBLK_LSTM - 1)) {
            g_bar = 0u;
            __threadfence();
            g_gen = gen + 1u;
        } else {
            while (g_gen == gen) { }
        }
        __threadfence();
    }
    __syncthreads();
}

// ---------------- kernel A: input projection GEMM ---------------------------
// X[dir][t][col][b] = sum_k hidden[b][t][k] * w_ih[dir][col][k] + b_ih + b_hh
// grid (24 n-tiles, 512 t, 2 dir), 256 threads, 64x64 tile, 4x4 per thread
__global__ void __launch_bounds__(256) proj_kernel(
    const float* __restrict__ hid,
    const float* __restrict__ wf, const float* __restrict__ wb,
    const float* __restrict__ bif, const float* __restrict__ bhf,
    const float* __restrict__ bib, const float* __restrict__ bhb)
{
    __shared__ float As[16][64];
    __shared__ float Bs[16][64];
    __shared__ float Cs[64][65];

    int t = blockIdx.y;
    int n0 = blockIdx.x * 64;
    int dir = blockIdx.z;
    const float* w = dir ? wb : wf;

    int tid = threadIdx.x;
    int tx = tid & 15;
    int ty = tid >> 4;

    float acc[4][4];
#pragma unroll
    for (int i = 0; i < 4; i++)
#pragma unroll
        for (int j = 0; j < 4; j++) acc[i][j] = 0.0f;

    int lb = tid >> 2;            // 0..63 : batch row (A) / out col (B)
    int lk = (tid & 3) * 4;       // 0,4,8,12
    const float* hidb = hid + (size_t)lb * TT * HH + (size_t)t * HH;
    const float* wrow = w + (size_t)(n0 + lb) * HH;

    for (int k0 = 0; k0 < HH; k0 += 16) {
        float4 a = *(const float4*)(hidb + k0 + lk);
        float4 bv = *(const float4*)(wrow + k0 + lk);
        As[lk + 0][lb] = a.x; As[lk + 1][lb] = a.y;
        As[lk + 2][lb] = a.z; As[lk + 3][lb] = a.w;
        Bs[lk + 0][lb] = bv.x; Bs[lk + 1][lb] = bv.y;
        Bs[lk + 2][lb] = bv.z; Bs[lk + 3][lb] = bv.w;
        __syncthreads();
#pragma unroll
        for (int k = 0; k < 16; k++) {
            float4 ra = *(const float4*)&As[k][ty * 4];
            float4 rb = *(const float4*)&Bs[k][tx * 4];
            acc[0][0] += ra.x * rb.x; acc[0][1] += ra.x * rb.y;
            acc[0][2] += ra.x * rb.z; acc[0][3] += ra.x * rb.w;
            acc[1][0] += ra.y * rb.x; acc[1][1] += ra.y * rb.y;
            acc[1][2] += ra.y * rb.z; acc[1][3] += ra.y * rb.w;
            acc[2][0] += ra.z * rb.x; acc[2][1] += ra.z * rb.y;
            acc[2][2] += ra.z * rb.z; acc[2][3] += ra.z * rb.w;
            acc[3][0] += ra.w * rb.x; acc[3][1] += ra.w * rb.y;
            acc[3][2] += ra.w * rb.z; acc[3][3] += ra.w * rb.w;
        }
        __syncthreads();
    }

#pragma unroll
    for (int i = 0; i < 4; i++)
#pragma unroll
        for (int j = 0; j < 4; j++)
            Cs[ty * 4 + i][tx * 4 + j] = acc[i][j];
    __syncthreads();

    const float* b1 = dir ? bib : bif;
    const float* b2 = dir ? bhb : bhf;
    float* outb = g_X + (((size_t)dir * TT + t) * G4 + n0) * BB;
#pragma unroll
    for (int e = 0; e < 16; e++) {
        int lin = e * 256 + tid;
        int cl = lin >> 6;
        int b = lin & 63;
        outb[cl * BB + b] = Cs[b][cl] + b1[n0 + cl] + b2[n0 + cl];
    }
}

// ---------------- kernel B: persistent BiLSTM recurrence ---------------------
// 96 CTAs: tile = (dir, 8 units x 4 gates = 32 cols) x 64 batch rows
__global__ void __launch_bounds__(256) lstm_kernel(
    const float* __restrict__ h0, const float* __restrict__ c0,
    const float* __restrict__ whf, const float* __restrict__ whb)
{
    __shared__ float Hs[64][33];
    __shared__ float Ws[32][32];

    int tile = blockIdx.x;
    int dir = tile / 48;
    int ug = tile % 48;                   // units [ug*8, ug*8+8)
    const float* W = dir ? whb : whf;

    int tid = threadIdx.x;
    int row = tid & 63;                   // batch
    int cg = tid >> 6;                    // 0..3, owns cols [cg*8, cg*8+8)
    int lc = tid & 31;                    // loader col
    int lk4 = (tid >> 5) * 4;             // loader k quad
    int wrow = (lc & 3) * LHD + ug * 8 + (lc >> 2);
    const float* wptr = W + (size_t)wrow * LHD;

    int hb = tid & 63;
    int hk = (tid >> 6) * 8;

    for (int s = 0; s < TT; s++) {
        int t = dir ? (TT - 1 - s) : s;
        int tp = dir ? (t + 1) : (t - 1);

        float acc[8];
#pragma unroll
        for (int i = 0; i < 8; i++) acc[i] = 0.0f;

        for (int kb = 0; kb < 12; kb++) {
            int k0 = kb * 32;
            if (s == 0) {
                const float* hz = h0 + (size_t)dir * BB * LHD + (size_t)hb * LHD;
#pragma unroll
                for (int i = 0; i < 8; i++) Hs[hb][hk + i] = hz[k0 + hk + i];
            } else {
                const float* hp = g_Hseq + (((size_t)dir * TT + tp) * LHD + k0) * BB;
#pragma unroll
                for (int i = 0; i < 8; i++) Hs[hb][hk + i] = hp[(hk + i) * BB + hb];
            }
            float4 wv = *(const float4*)(wptr + k0 + lk4);
            Ws[lk4 + 0][lc] = wv.x; Ws[lk4 + 1][lc] = wv.y;
            Ws[lk4 + 2][lc] = wv.z; Ws[lk4 + 3][lc] = wv.w;
            __syncthreads();
#pragma unroll
            for (int k = 0; k < 32; k++) {
                float a = Hs[row][k];
                float4 w0 = *(const float4*)&Ws[k][cg * 8];
                float4 w1 = *(const float4*)&Ws[k][cg * 8 + 4];
                acc[0] += a * w0.x; acc[1] += a * w0.y;
                acc[2] += a * w0.z; acc[3] += a * w0.w;
                acc[4] += a * w1.x; acc[5] += a * w1.y;
                acc[6] += a * w1.z; acc[7] += a * w1.w;
            }
            __syncthreads();
        }

        // epilogue: this thread owns batch=row, units j0, j0+1 (all 4 gates)
        const float* xb = g_X + (((size_t)dir * TT + t) * G4) * BB;
#pragma unroll
        for (int u = 0; u < 2; u++) {
            int j = ug * 8 + cg * 2 + u;
            float gi = acc[u * 4 + 0] + xb[(0 * LHD + j) * BB + row];
            float gf = acc[u * 4 + 1] + xb[(1 * LHD + j) * BB + row];
            float gg = acc[u * 4 + 2] + xb[(2 * LHD + j) * BB + row];
            float go = acc[u * 4 + 3] + xb[(3 * LHD + j) * BB + row];
            float cp = (s == 0) ? c0[(size_t)dir * BB * LHD + (size_t)row * LHD + j]
                                : g_C[((size_t)dir * BB + row) * LHD + j];
            float cn = sigm(gf) * cp + sigm(gi) * tanhf(gg);
            float hn = sigm(go) * tanhf(cn);
            g_C[((size_t)dir * BB + row) * LHD + j] = cn;
            g_Hseq[(((size_t)dir * TT + t) * LHD + j) * BB + row] = hn;
        }
        gridbar();
    }
}

// ---------------- kernel C: FC emissions -------------------------------------
// feats[b][t][l] = sum_j hf*fcw[l][j] + hb*fcw[l][384+j] + fcb[l]
__global__ void __launch_bounds__(256) fc_kernel(
    const float* __restrict__ fcw, const float* __restrict__ fcb)
{
    __shared__ float Wsm[NLAB * 768];
    __shared__ float Bsm[NLAB];

    int t = blockIdx.x;
    int tid = threadIdx.x;
    for (int i = tid; i < NLAB * 768; i += 256) Wsm[i] = fcw[i];
    if (tid < NLAB) Bsm[tid] = fcb[tid];
    __syncthreads();

    int b = tid & 63;
    int lg = tid >> 6;  // 3 labels each
    float acc[3];
#pragma unroll
    for (int q = 0; q < 3; q++) acc[q] = Bsm[lg * 3 + q];

    const float* hf = g_Hseq + ((size_t)0 * TT + t) * LHD * BB;
    const float* hb = g_Hseq + ((size_t)1 * TT + t) * LHD * BB;
    for (int j = 0; j < LHD; j++) {
        float vf = hf[j * BB + b];
        float vb = hb[j * BB + b];
#pragma unroll
        for (int q = 0; q < 3; q++) {
            int l = lg * 3 + q;
            acc[q] += vf * Wsm[l * 768 + j] + vb * Wsm[l * 768 + LHD + j];
        }
    }
#pragma unroll
    for (int q = 0; q < 3; q++)
        g_feats[((size_t)b * TT + t) * NLAB + lg * 3 + q] = acc[q];
}

// ---------------- kernel D: Viterbi ------------------------------------------
__global__ void __launch_bounds__(128) viterbi_kernel(
    const float* __restrict__ trans, const int* __restrict__ start_ptr,
    float* __restrict__ out)
{
    __shared__ float sf[TT * NLAB];
    __shared__ float ts[NLAB * NLAB];
    __shared__ float fv[NLAB];
    __shared__ unsigned char ptr[TT * NLAB];

    int b = blockIdx.x;
    int tid = threadIdx.x;
    for (int i = tid; i < TT * NLAB; i += 128) sf[i] = g_feats[(size_t)b * TT * NLAB + i];
    for (int i = tid; i < NLAB * NLAB; i += 128) ts[i] = trans[i];
    int start = *start_ptr;
    if (tid < NLAB) fv[tid] = (tid == start) ? 0.0f : NEGV;
    __syncthreads();

    if (tid < 32) {
        for (int t = 1; t < TT; t++) {
            float best = 0.0f; int arg = 0;
            if (tid < NLAB) {
                best = ts[tid * NLAB + 0] + fv[0]; arg = 0;
#pragma unroll
                for (int p = 1; p < NLAB; p++) {
                    float v = ts[tid * NLAB + p] + fv[p];
                    if (v > best) { best = v; arg = p; }
                }
                best += sf[t * NLAB + tid];
            }
            __syncwarp();
            if (tid < NLAB) {
                fv[tid] = best;
                ptr[t * NLAB + tid] = (unsigned char)arg;
            }
            __syncwarp();
        }
        if (tid == 0) {
            float bs = fv[0]; int last = 0;
            for (int l = 1; l < NLAB; l++)
                if (fv[l] > bs) { bs = fv[l]; last = l; }
            out[b] = bs;
            float* pp = out + 64 + (size_t)b * TT;
            int cur = last;
            pp[TT - 1] = (float)cur;
            for (int t = TT - 2; t >= 0; t--) {
                cur = ptr[(t + 1) * NLAB + cur];
                pp[t] = (float)cur;
            }
        }
    }
}

// ---------------- launch ------------------------------------------------------
extern "C" void kernel_launch(void* const* d_in, const int* in_sizes, int n_in,
                              void* d_out, int out_size)
{
    const float* hidden = (const float*)d_in[0];
    const float* h0     = (const float*)d_in[1];
    const float* c0     = (const float*)d_in[2];
    const float* w_ih_f = (const float*)d_in[3];
    const float* w_hh_f = (const float*)d_in[4];
    const float* b_ih_f = (const float*)d_in[5];
    const float* b_hh_f = (const float*)d_in[6];
    const float* w_ih_b = (const float*)d_in[7];
    const float* w_hh_b = (const float*)d_in[8];
    const float* b_ih_b = (const float*)d_in[9];
    const float* b_hh_b = (const float*)d_in[10];
    const float* fc_w   = (const float*)d_in[11];
    const float* fc_b   = (const float*)d_in[12];
    const float* transitions = (const float*)d_in[13];
    const int*   start_idx   = (const int*)d_in[14];

    dim3 gridA(24, 512, 2);
    proj_kernel<<<gridA, 256>>>(hidden, w_ih_f, w_ih_b,
                                b_ih_f, b_hh_f, b_ih_b, b_hh_b);
    lstm_kernel<<<NBLK_LSTM, 256>>>(h0, c0, w_hh_f, w_hh_b);
    fc_kernel<<<512, 256>>>(fc_w, fc_b);
    viterbi_kernel<<<64, 128>>>(transitions, start_idx, (float*)d_out);
}

// round 3
// speedup vs baseline: 1.3808x; 1.3808x over previous
#include <cuda_runtime.h>

// Problem constants
#define TT 512
#define BB 64
#define HH 768
#define LHD 384
#define G4 1536
#define NLAB 12
#define NEGV (-1000.0f)
#define NBLK_LSTM 96

// ---------------- scratch (static device memory; no allocation) -------------
// X[dir][t][col][b], col = gate*384 + j   (2*512*1536*64)
__device__ float g_X[100663296];
// Hseq[dir][t][j][b]                      (2*512*384*64)
__device__ float g_Hseq[25165824];
// C[dir][j][b]
__device__ float g_C[2 * 384 * 64];
// feats[b][t][l]
__device__ float g_feats[64 * 512 * 12];

__device__ unsigned g_bar = 0u;
__device__ volatile unsigned g_gen = 0u;

__device__ __forceinline__ float sigm(float x) {
    return 1.0f / (1.0f + __expf(-x));
}

// packed f32x2 FMA (Blackwell): d = a*b + c on both lanes, full fp32 accuracy
__device__ __forceinline__ float2 ffma2(float2 a, float2 b, float2 c) {
    union U { float2 f; unsigned long long u; };
    U A, B, C, D;
    A.f = a; B.f = b; C.f = c;
    asm("fma.rn.f32x2 %0, %1, %2, %3;"
        : "=l"(D.u) : "l"(A.u), "l"(B.u), "l"(C.u));
    return D.f;
}

__device__ __forceinline__ void gridbar() {
    __syncthreads();
    if (threadIdx.x == 0) {
        __threadfence();
        unsigned gen = g_gen;
        if (atomicAdd(&g_bar, 1u) == (unsigned)(NBLK_LSTM - 1)) {
            g_bar = 0u;
            __threadfence();
            g_gen = gen + 1u;
        } else {
            while (g_gen == gen) { }
        }
        __threadfence();
    }
    __syncthreads();
}

// ---------------- kernel A: input projection GEMM ---------------------------
// X[dir][t][col][b] = sum_k hidden[b][t][k] * w_ih[dir][col][k] + b_ih + b_hh
// grid (12 n-tiles, 512 t, 2 dir), 256 threads, 128col x 64batch tile,
// 4 batch x 8 cols per thread, FFMA2 on col pairs.
__global__ void __launch_bounds__(256) proj_kernel(
    const float* __restrict__ hid,
    const float* __restrict__ wf, const float* __restrict__ wb,
    const float* __restrict__ bif, const float* __restrict__ bhf,
    const float* __restrict__ bib, const float* __restrict__ bhb)
{
    __shared__ float smempool[64 * 129];   // 33024B; aliases As|Bs then Cs
    float* As = smempool;                   // [16][64]
    float* Bs = smempool + 16 * 64;         // [16][128]

    int t = blockIdx.y;
    int n0 = blockIdx.x * 128;
    int dir = blockIdx.z;
    const float* w = dir ? wb : wf;

    int tid = threadIdx.x;
    int tx = tid & 15;        // col group: cols tx*8 .. tx*8+7
    int ty = tid >> 4;        // batch group: batch ty*4 .. ty*4+3

    float2 acc[4][4];
#pragma unroll
    for (int i = 0; i < 4; i++)
#pragma unroll
        for (int j = 0; j < 4; j++) acc[i][j] = make_float2(0.f, 0.f);

    // A loader: lb batch 0..63, lk k-quad
    int lb = tid >> 2;
    int lk = (tid & 3) * 4;
    const float* hidb = hid + (size_t)lb * TT * HH + (size_t)t * HH;
    // B loader: bc col 0..127, bk k-oct
    int bc = tid >> 1;
    int bk = (tid & 1) * 8;
    const float* wrow = w + (size_t)(n0 + bc) * HH;

    for (int k0 = 0; k0 < HH; k0 += 16) {
        float4 a = *(const float4*)(hidb + k0 + lk);
        As[(lk + 0) * 64 + lb] = a.x; As[(lk + 1) * 64 + lb] = a.y;
        As[(lk + 2) * 64 + lb] = a.z; As[(lk + 3) * 64 + lb] = a.w;
        float4 b0 = *(const float4*)(wrow + k0 + bk);
        float4 b1 = *(const float4*)(wrow + k0 + bk + 4);
        Bs[(bk + 0) * 128 + bc] = b0.x; Bs[(bk + 1) * 128 + bc] = b0.y;
        Bs[(bk + 2) * 128 + bc] = b0.z; Bs[(bk + 3) * 128 + bc] = b0.w;
        Bs[(bk + 4) * 128 + bc] = b1.x; Bs[(bk + 5) * 128 + bc] = b1.y;
        Bs[(bk + 6) * 128 + bc] = b1.z; Bs[(bk + 7) * 128 + bc] = b1.w;
        __syncthreads();
#pragma unroll
        for (int k = 0; k < 16; k++) {
            float4 ra  = *(const float4*)&As[k * 64 + ty * 4];
            float4 rb0 = *(const float4*)&Bs[k * 128 + tx * 8];
            float4 rb1 = *(const float4*)&Bs[k * 128 + tx * 8 + 4];
            float2 bp0 = make_float2(rb0.x, rb0.y);
            float2 bp1 = make_float2(rb0.z, rb0.w);
            float2 bp2 = make_float2(rb1.x, rb1.y);
            float2 bp3 = make_float2(rb1.z, rb1.w);
            float2 aa;
            aa = make_float2(ra.x, ra.x);
            acc[0][0] = ffma2(aa, bp0, acc[0][0]);
            acc[0][1] = ffma2(aa, bp1, acc[0][1]);
            acc[0][2] = ffma2(aa, bp2, acc[0][2]);
            acc[0][3] = ffma2(aa, bp3, acc[0][3]);
            aa = make_float2(ra.y, ra.y);
            acc[1][0] = ffma2(aa, bp0, acc[1][0]);
            acc[1][1] = ffma2(aa, bp1, acc[1][1]);
            acc[1][2] = ffma2(aa, bp2, acc[1][2]);
            acc[1][3] = ffma2(aa, bp3, acc[1][3]);
            aa = make_float2(ra.z, ra.z);
            acc[2][0] = ffma2(aa, bp0, acc[2][0]);
            acc[2][1] = ffma2(aa, bp1, acc[2][1]);
            acc[2][2] = ffma2(aa, bp2, acc[2][2]);
            acc[2][3] = ffma2(aa, bp3, acc[2][3]);
            aa = make_float2(ra.w, ra.w);
            acc[3][0] = ffma2(aa, bp0, acc[3][0]);
            acc[3][1] = ffma2(aa, bp1, acc[3][1]);
            acc[3][2] = ffma2(aa, bp2, acc[3][2]);
            acc[3][3] = ffma2(aa, bp3, acc[3][3]);
        }
        __syncthreads();
    }

    // epilogue via staging buffer Cs[64][129] (aliases As/Bs)
    float* Cs = smempool;
#pragma unroll
    for (int i = 0; i < 4; i++)
#pragma unroll
        for (int p = 0; p < 4; p++) {
            Cs[(ty * 4 + i) * 129 + tx * 8 + 2 * p]     = acc[i][p].x;
            Cs[(ty * 4 + i) * 129 + tx * 8 + 2 * p + 1] = acc[i][p].y;
        }
    __syncthreads();

    const float* b1 = dir ? bib : bif;
    const float* b2 = dir ? bhb : bhf;
    float* outb = g_X + (((size_t)dir * TT + t) * G4 + n0) * BB;
#pragma unroll
    for (int e = 0; e < 8; e++) {
        int idx = e * 256 + tid;
        int c = idx >> 4;
        int b4 = (idx & 15) * 4;
        float bias = b1[n0 + c] + b2[n0 + c];
        float4 v;
        v.x = Cs[(b4 + 0) * 129 + c] + bias;
        v.y = Cs[(b4 + 1) * 129 + c] + bias;
        v.z = Cs[(b4 + 2) * 129 + c] + bias;
        v.w = Cs[(b4 + 3) * 129 + c] + bias;
        *(float4*)&outb[c * 64 + b4] = v;
    }
}

// ---------------- kernel B: persistent BiLSTM recurrence ---------------------
// 96 CTAs: tile = (dir, 32 cols) x 64 batch. W slice preloaded to smem once.
// Dynamic smem: Ws[384][32] (48KB) + Hs[2][64][64] (32KB) = 80KB.
__global__ void __launch_bounds__(256) lstm_kernel(
    const float* __restrict__ h0, const float* __restrict__ c0,
    const float* __restrict__ whf, const float* __restrict__ whb)
{
    extern __shared__ float sm[];
    float* Ws = sm;                 // [384][32]
    float* Hb = sm + 384 * 32;      // [2][64][64]

    int tile = blockIdx.x;
    int dir = tile / 48;
    int ug = tile % 48;                   // units [ug*8, ug*8+8)
    const float* W = dir ? whb : whf;

    int tid = threadIdx.x;
    int row = tid & 63;                   // batch
    int cg = tid >> 6;                    // 0..3, owns cols [cg*8, cg*8+8)

    // ---- one-time weight preload: col c -> W row (c&3)*384 + ug*8 + (c>>2)
    {
        int c = tid & 31;
        int kg = tid >> 5;                // 0..7, k range kg*48..+47
        int wr = (c & 3) * LHD + ug * 8 + (c >> 2);
        const float* src = W + (size_t)wr * LHD + kg * 48;
#pragma unroll
        for (int i = 0; i < 12; i++) {
            float4 v = *(const float4*)(src + i * 4);
            int k = kg * 48 + i * 4;
            Ws[(k + 0) * 32 + c] = v.x;
            Ws[(k + 1) * 32 + c] = v.y;
            Ws[(k + 2) * 32 + c] = v.z;
            Ws[(k + 3) * 32 + c] = v.w;
        }
    }

    for (int s = 0; s < TT; s++) {
        int t = dir ? (TT - 1 - s) : s;
        int tp = dir ? (t + 1) : (t - 1);
        const float* hp = g_Hseq + (((size_t)dir * TT + tp) * LHD) * BB;

        // ---- load chunk 0 (k 0..63) into buf 0
        if (s == 0) {
            int b = tid & 63;
            int kbase = (tid >> 6) * 16;
            const float* h0b = h0 + ((size_t)dir * BB + b) * LHD;
#pragma unroll
            for (int i = 0; i < 16; i += 4) {
                float4 v = *(const float4*)(h0b + kbase + i);
                Hb[(kbase + i + 0) * 64 + b] = v.x;
                Hb[(kbase + i + 1) * 64 + b] = v.y;
                Hb[(kbase + i + 2) * 64 + b] = v.z;
                Hb[(kbase + i + 3) * 64 + b] = v.w;
            }
        } else {
#pragma unroll
            for (int i = 0; i < 4; i++) {
                int f = tid + i * 256;
                int k = f >> 4;
                int b4 = (f & 15) * 4;
                float4 v = *(const float4*)&hp[k * 64 + b4];
                *(float4*)&Hb[k * 64 + b4] = v;
            }
        }
        __syncthreads();

        float2 acc[4];
#pragma unroll
        for (int p = 0; p < 4; p++) acc[p] = make_float2(0.f, 0.f);

        for (int kb = 0; kb < 6; kb++) {
            int cur = kb & 1;
            // prefetch next chunk into registers (hidden behind compute)
            float4 pf[4];
            bool doPf = (s > 0) && (kb < 5);
            if (doPf) {
#pragma unroll
                for (int i = 0; i < 4; i++) {
                    int f = tid + i * 256;
                    int k = f >> 4;
                    int b4 = (f & 15) * 4;
                    pf[i] = *(const float4*)&hp[((kb + 1) * 64 + k) * 64 + b4];
                }
            }
            const float* hc = Hb + cur * 4096;
            const float* wkb = Ws + (kb * 64) * 32 + cg * 8;
#pragma unroll 16
            for (int k = 0; k < 64; k++) {
                float a = hc[k * 64 + row];
                float2 aa = make_float2(a, a);
                float4 w0 = *(const float4*)&wkb[k * 32];
                float4 w1 = *(const float4*)&wkb[k * 32 + 4];
                acc[0] = ffma2(aa, make_float2(w0.x, w0.y), acc[0]);
                acc[1] = ffma2(aa, make_float2(w0.z, w0.w), acc[1]);
                acc[2] = ffma2(aa, make_float2(w1.x, w1.y), acc[2]);
                acc[3] = ffma2(aa, make_float2(w1.z, w1.w), acc[3]);
            }
            if (kb < 5) {
                float* hn = Hb + (cur ^ 1) * 4096;
                if (doPf) {
#pragma unroll
                    for (int i = 0; i < 4; i++) {
                        int f = tid + i * 256;
                        int k = f >> 4;
                        int b4 = (f & 15) * 4;
                        *(float4*)&hn[k * 64 + b4] = pf[i];
                    }
                } else {
                    // s == 0: load next chunk from h0
                    int b = tid & 63;
                    int kbase = (kb + 1) * 64 + (tid >> 6) * 16;
                    const float* h0b = h0 + ((size_t)dir * BB + b) * LHD;
#pragma unroll
                    for (int i = 0; i < 16; i += 4) {
                        float4 v = *(const float4*)(h0b + kbase + i);
                        int kk = (tid >> 6) * 16 + i;
                        hn[(kk + 0) * 64 + b] = v.x;
                        hn[(kk + 1) * 64 + b] = v.y;
                        hn[(kk + 2) * 64 + b] = v.z;
                        hn[(kk + 3) * 64 + b] = v.w;
                    }
                }
            }
            __syncthreads();
        }

        // epilogue: thread owns batch=row, units ug*8+cg*2+{0,1}, all 4 gates
        // col pairs: acc[2u] = (i,f), acc[2u+1] = (g,o) for unit u
        const float* xb = g_X + (((size_t)dir * TT + t) * G4) * BB;
#pragma unroll
        for (int u = 0; u < 2; u++) {
            int j = ug * 8 + cg * 2 + u;
            float gi = acc[2 * u].x     + xb[(0 * LHD + j) * BB + row];
            float gf = acc[2 * u].y     + xb[(1 * LHD + j) * BB + row];
            float gg = acc[2 * u + 1].x + xb[(2 * LHD + j) * BB + row];
            float go = acc[2 * u + 1].y + xb[(3 * LHD + j) * BB + row];
            float cp = (s == 0) ? c0[((size_t)dir * BB + row) * LHD + j]
                                : g_C[((size_t)dir * LHD + j) * BB + row];
            float cn = sigm(gf) * cp + sigm(gi) * tanhf(gg);
            float hn = sigm(go) * tanhf(cn);
            g_C[((size_t)dir * LHD + j) * BB + row] = cn;
            g_Hseq[(((size_t)dir * TT + t) * LHD + j) * BB + row] = hn;
        }
        gridbar();
    }
}

// ---------------- kernel C: FC emissions -------------------------------------
__global__ void __launch_bounds__(256) fc_kernel(
    const float* __restrict__ fcw, const float* __restrict__ fcb)
{
    __shared__ float Wsm[NLAB * 768];
    __shared__ float Bsm[NLAB];

    int t = blockIdx.x;
    int tid = threadIdx.x;
    for (int i = tid; i < NLAB * 768; i += 256) Wsm[i] = fcw[i];
    if (tid < NLAB) Bsm[tid] = fcb[tid];
    __syncthreads();

    int b = tid & 63;
    int lg = tid >> 6;  // 3 labels each
    float acc[3];
#pragma unroll
    for (int q = 0; q < 3; q++) acc[q] = Bsm[lg * 3 + q];

    const float* hf = g_Hseq + ((size_t)0 * TT + t) * LHD * BB;
    const float* hb = g_Hseq + ((size_t)1 * TT + t) * LHD * BB;
    for (int j = 0; j < LHD; j++) {
        float vf = hf[j * BB + b];
        float vb = hb[j * BB + b];
#pragma unroll
        for (int q = 0; q < 3; q++) {
            int l = lg * 3 + q;
            acc[q] += vf * Wsm[l * 768 + j] + vb * Wsm[l * 768 + LHD + j];
        }
    }
#pragma unroll
    for (int q = 0; q < 3; q++)
        g_feats[((size_t)b * TT + t) * NLAB + lg * 3 + q] = acc[q];
}

// ---------------- kernel D: Viterbi ------------------------------------------
__global__ void __launch_bounds__(128) viterbi_kernel(
    const float* __restrict__ trans, const int* __restrict__ start_ptr,
    float* __restrict__ out)
{
    __shared__ float sf[TT * NLAB];
    __shared__ float ts[NLAB * NLAB];
    __shared__ float fv[NLAB];
    __shared__ unsigned char ptr[TT * NLAB];

    int b = blockIdx.x;
    int tid = threadIdx.x;
    for (int i = tid; i < TT * NLAB; i += 128) sf[i] = g_feats[(size_t)b * TT * NLAB + i];
    for (int i = tid; i < NLAB * NLAB; i += 128) ts[i] = trans[i];
    int start = *start_ptr;
    if (tid < NLAB) fv[tid] = (tid == start) ? 0.0f : NEGV;
    __syncthreads();

    if (tid < 32) {
        for (int t = 1; t < TT; t++) {
            float best = 0.0f; int arg = 0;
            if (tid < NLAB) {
                best = ts[tid * NLAB + 0] + fv[0]; arg = 0;
#pragma unroll
                for (int p = 1; p < NLAB; p++) {
                    float v = ts[tid * NLAB + p] + fv[p];
                    if (v > best) { best = v; arg = p; }
                }
                best += sf[t * NLAB + tid];
            }
            __syncwarp();
            if (tid < NLAB) {
                fv[tid] = best;
                ptr[t * NLAB + tid] = (unsigned char)arg;
            }
            __syncwarp();
        }
        if (tid == 0) {
            float bs = fv[0]; int last = 0;
            for (int l = 1; l < NLAB; l++)
                if (fv[l] > bs) { bs = fv[l]; last = l; }
            out[b] = bs;
            float* pp = out + 64 + (size_t)b * TT;
            int cur = last;
            pp[TT - 1] = (float)cur;
            for (int t = TT - 2; t >= 0; t--) {
                cur = ptr[(t + 1) * NLAB + cur];
                pp[t] = (float)cur;
            }
        }
    }
}

// ---------------- launch ------------------------------------------------------
extern "C" void kernel_launch(void* const* d_in, const int* in_sizes, int n_in,
                              void* d_out, int out_size)
{
    const float* hidden = (const float*)d_in[0];
    const float* h0     = (const float*)d_in[1];
    const float* c0     = (const float*)d_in[2];
    const float* w_ih_f = (const float*)d_in[3];
    const float* w_hh_f = (const float*)d_in[4];
    const float* b_ih_f = (const float*)d_in[5];
    const float* b_hh_f = (const float*)d_in[6];
    const float* w_ih_b = (const float*)d_in[7];
    const float* w_hh_b = (const float*)d_in[8];
    const float* b_ih_b = (const float*)d_in[9];
    const float* b_hh_b = (const float*)d_in[10];
    const float* fc_w   = (const float*)d_in[11];
    const float* fc_b   = (const float*)d_in[12];
    const float* transitions = (const float*)d_in[13];
    const int*   start_idx   = (const int*)d_in[14];

    static int smem_set = 0;
    int lstm_smem = (384 * 32 + 2 * 64 * 64) * sizeof(float);  // 81920
    if (!smem_set) {
        cudaFuncSetAttribute(lstm_kernel,
                             cudaFuncAttributeMaxDynamicSharedMemorySize,
                             lstm_smem);
        smem_set = 1;
    }

    dim3 gridA(12, 512, 2);
    proj_kernel<<<gridA, 256>>>(hidden, w_ih_f, w_ih_b,
                                b_ih_f, b_hh_f, b_ih_b, b_hh_b);
    lstm_kernel<<<NBLK_LSTM, 256, lstm_smem>>>(h0, c0, w_hh_f, w_hh_b);
    fc_kernel<<<512, 256>>>(fc_w, fc_b);
    viterbi_kernel<<<64, 128>>>(transitions, start_idx, (float*)d_out);
}